// round 1
// baseline (speedup 1.0000x reference)
#include <cuda_runtime.h>

// Problem dims (fixed by the reference)
#define BB 2
#define SS 2048
#define DDIM 1024
#define HH 16
#define DH 64
#define MM (BB*SS)   // 4096

// Scratch (allocation-free rule: __device__ globals)
__device__ float g_Qh[BB*HH*SS*DH];   // [B,H,S,DH]
__device__ float g_Kh[BB*HH*SS*DH];
__device__ float g_Vh[BB*HH*SS*DH];
__device__ float g_ctx[MM*DDIM];      // [B,S,D]

// ---------------------------------------------------------------------------
// GEMM: Y = X[M,K] @ W[K,N] + bias, M=4096, N=K=1024.
// 128x128 tile, BK=16, 256 threads, 8x8 per thread.
// headsplit=1: write Y into [B,H,S,DH] layout (for Q/K/V).
// ---------------------------------------------------------------------------
__global__ __launch_bounds__(256) void gemm_bias_kernel(
    const float* __restrict__ X,
    const float* __restrict__ W,
    const float* __restrict__ bias,
    float* __restrict__ Y,
    int headsplit)
{
    __shared__ float As[16][132];   // A stored transposed: As[k][m]
    __shared__ float Bs[16][128];   // Bs[k][n]

    const int t  = threadIdx.x;
    const int tx = t & 15;          // 16 col groups of 8
    const int ty = t >> 4;          // 16 row groups of 8
    const int rowBase = blockIdx.y * 128;
    const int colBase = blockIdx.x * 128;

    float acc[8][8];
    #pragma unroll
    for (int i = 0; i < 8; ++i)
        #pragma unroll
        for (int j = 0; j < 8; ++j) acc[i][j] = 0.0f;

    for (int k0 = 0; k0 < DDIM; k0 += 16) {
        // Load A tile: 128 rows x 16 k = 512 float4, 2 per thread
        #pragma unroll
        for (int u = 0; u < 2; ++u) {
            int id = t + u * 256;
            int r  = id >> 2;
            int kq = (id & 3) << 2;
            float4 a = *(const float4*)(X + (size_t)(rowBase + r) * DDIM + k0 + kq);
            As[kq + 0][r] = a.x;
            As[kq + 1][r] = a.y;
            As[kq + 2][r] = a.z;
            As[kq + 3][r] = a.w;
        }
        // Load B tile: 16 k x 128 cols = 512 float4, 2 per thread
        #pragma unroll
        for (int u = 0; u < 2; ++u) {
            int id = t + u * 256;
            int r  = id >> 5;
            int c4 = (id & 31) << 2;
            *(float4*)&Bs[r][c4] =
                *(const float4*)(W + (size_t)(k0 + r) * DDIM + colBase + c4);
        }
        __syncthreads();

        #pragma unroll
        for (int kk = 0; kk < 16; ++kk) {
            float af[8], bf[8];
            *(float4*)&af[0] = *(float4*)&As[kk][ty * 8 + 0];
            *(float4*)&af[4] = *(float4*)&As[kk][ty * 8 + 4];
            *(float4*)&bf[0] = *(float4*)&Bs[kk][tx * 8 + 0];
            *(float4*)&bf[4] = *(float4*)&Bs[kk][tx * 8 + 4];
            #pragma unroll
            for (int i = 0; i < 8; ++i)
                #pragma unroll
                for (int j = 0; j < 8; ++j)
                    acc[i][j] += af[i] * bf[j];
        }
        __syncthreads();
    }

    // Epilogue
    const int col0 = colBase + tx * 8;
    float bv[8];
    #pragma unroll
    for (int j = 0; j < 8; ++j) bv[j] = bias[col0 + j];

    if (!headsplit) {
        #pragma unroll
        for (int i = 0; i < 8; ++i) {
            int row = rowBase + ty * 8 + i;
            float* outp = Y + (size_t)row * DDIM + col0;
            float4 o0, o1;
            o0.x = acc[i][0] + bv[0]; o0.y = acc[i][1] + bv[1];
            o0.z = acc[i][2] + bv[2]; o0.w = acc[i][3] + bv[3];
            o1.x = acc[i][4] + bv[4]; o1.y = acc[i][5] + bv[5];
            o1.z = acc[i][6] + bv[6]; o1.w = acc[i][7] + bv[7];
            *(float4*)(outp + 0) = o0;
            *(float4*)(outp + 4) = o1;
        }
    } else {
        // col0 is a multiple of 8, so the 8-col group lies within one head.
        const int hh = col0 >> 6;       // col0 / 64
        const int dh = col0 & 63;
        #pragma unroll
        for (int i = 0; i < 8; ++i) {
            int row = rowBase + ty * 8 + i;
            int b   = row >> 11;        // row / 2048
            int s   = row & 2047;
            float* outp = Y + ((size_t)((b * HH + hh) * SS + s)) * DH + dh;
            float4 o0, o1;
            o0.x = acc[i][0] + bv[0]; o0.y = acc[i][1] + bv[1];
            o0.z = acc[i][2] + bv[2]; o0.w = acc[i][3] + bv[3];
            o1.x = acc[i][4] + bv[4]; o1.y = acc[i][5] + bv[5];
            o1.z = acc[i][6] + bv[6]; o1.w = acc[i][7] + bv[7];
            *(float4*)(outp + 0) = o0;
            *(float4*)(outp + 4) = o1;
        }
    }
}

// ---------------------------------------------------------------------------
// Flash-attention (fp32, causal). One CTA = 64 q-rows of one (b,h).
// KV processed in blocks of 32. 128 threads:
//   sy = t>>3 (16 groups) -> q rows sy*4..sy*4+3
//   sx = t&7             -> S-tile k cols sx*4..+3 / O-tile d cols sx*8..+7
// ---------------------------------------------------------------------------
__global__ __launch_bounds__(128) void attn_kernel()
{
    __shared__ float Qs [64][68];   // [q][d]
    __shared__ float Kts[64][33];   // [d][k]  (transposed K block)
    __shared__ float Vs [32][68];   // [k][d]
    __shared__ float Ps [64][36];   // [q][k]

    const int qb = 31 - blockIdx.x;   // heavy (late) q-blocks first
    const int h  = blockIdx.y;
    const int b  = blockIdx.z;

    const float* Qp  = g_Qh + ((size_t)(b * HH + h) * SS + qb * 64) * DH;
    const float* Kp0 = g_Kh + ((size_t)(b * HH + h) * SS) * DH;
    const float* Vp0 = g_Vh + ((size_t)(b * HH + h) * SS) * DH;

    const int t  = threadIdx.x;
    const int sy = t >> 3;
    const int sx = t & 7;

    // Load Q block: 64x64 = 1024 float4, 8 per thread
    #pragma unroll
    for (int u = 0; u < 8; ++u) {
        int id = t + u * 128;
        int r  = id >> 4;
        int c4 = (id & 15) << 2;
        *(float4*)&Qs[r][c4] = *(const float4*)(Qp + r * DH + c4);
    }

    float acc[4][8];
    #pragma unroll
    for (int i = 0; i < 4; ++i)
        #pragma unroll
        for (int jd = 0; jd < 8; ++jd) acc[i][jd] = 0.0f;
    float mrow[4] = {-1e30f, -1e30f, -1e30f, -1e30f};
    float lrow[4] = {0.0f, 0.0f, 0.0f, 0.0f};

    const int nkv = 2 * qb + 2;   // causal: kv blocks 0 .. 2*qb+1
    for (int j = 0; j < nkv; ++j) {
        __syncthreads();   // previous iter done reading Kts/Vs/Ps
        const float* Kp = Kp0 + (size_t)j * 32 * DH;
        const float* Vp = Vp0 + (size_t)j * 32 * DH;
        // Load K (transposed) and V: 32x64 each = 512 float4, 4 per thread
        #pragma unroll
        for (int u = 0; u < 4; ++u) {
            int id = t + u * 128;
            int r  = id >> 4;
            int c4 = (id & 15) << 2;
            float4 kv = *(const float4*)(Kp + r * DH + c4);
            Kts[c4 + 0][r] = kv.x;
            Kts[c4 + 1][r] = kv.y;
            Kts[c4 + 2][r] = kv.z;
            Kts[c4 + 3][r] = kv.w;
            *(float4*)&Vs[r][c4] = *(const float4*)(Vp + r * DH + c4);
        }
        __syncthreads();

        // S = Q K^T  (4x4 per thread over a 64x32 tile)
        float s[4][4];
        #pragma unroll
        for (int i = 0; i < 4; ++i)
            #pragma unroll
            for (int u = 0; u < 4; ++u) s[i][u] = 0.0f;

        #pragma unroll 8
        for (int d = 0; d < 64; ++d) {
            float kf[4], qf[4];
            #pragma unroll
            for (int u = 0; u < 4; ++u) kf[u] = Kts[d][sx * 4 + u];
            #pragma unroll
            for (int i = 0; i < 4; ++i) qf[i] = Qs[sy * 4 + i][d];
            #pragma unroll
            for (int i = 0; i < 4; ++i)
                #pragma unroll
                for (int u = 0; u < 4; ++u)
                    s[i][u] += qf[i] * kf[u];
        }

        // Scale + CTRL mask (-10000 above the diagonal), matching reference
        const int qg0 = qb * 64 + sy * 4;
        const int kg0 = j * 32 + sx * 4;
        #pragma unroll
        for (int i = 0; i < 4; ++i)
            #pragma unroll
            for (int u = 0; u < 4; ++u) {
                s[i][u] *= 0.125f;   // 1/sqrt(64)
                if (kg0 + u > qg0 + i) s[i][u] -= 10000.0f;
            }

        // Online softmax (per q-row, reduced over the 8 sx lanes)
        #pragma unroll
        for (int i = 0; i < 4; ++i) {
            float m = fmaxf(fmaxf(s[i][0], s[i][1]), fmaxf(s[i][2], s[i][3]));
            m = fmaxf(m, __shfl_xor_sync(0xffffffffu, m, 1));
            m = fmaxf(m, __shfl_xor_sync(0xffffffffu, m, 2));
            m = fmaxf(m, __shfl_xor_sync(0xffffffffu, m, 4));
            float mnew  = fmaxf(mrow[i], m);
            float alpha = __expf(mrow[i] - mnew);
            mrow[i] = mnew;
            float lc = 0.0f;
            #pragma unroll
            for (int u = 0; u < 4; ++u) {
                s[i][u] = __expf(s[i][u] - mnew);
                lc += s[i][u];
            }
            lc += __shfl_xor_sync(0xffffffffu, lc, 1);
            lc += __shfl_xor_sync(0xffffffffu, lc, 2);
            lc += __shfl_xor_sync(0xffffffffu, lc, 4);
            lrow[i] = lrow[i] * alpha + lc;
            #pragma unroll
            for (int jd = 0; jd < 8; ++jd) acc[i][jd] *= alpha;
            #pragma unroll
            for (int u = 0; u < 4; ++u) Ps[sy * 4 + i][sx * 4 + u] = s[i][u];
        }
        __syncthreads();

        // O += P @ V   (each thread: 4 q-rows x 8 d-cols)
        #pragma unroll 4
        for (int kk = 0; kk < 32; ++kk) {
            float vf[8];
            *(float4*)&vf[0] = *(float4*)&Vs[kk][sx * 8 + 0];
            *(float4*)&vf[4] = *(float4*)&Vs[kk][sx * 8 + 4];
            #pragma unroll
            for (int i = 0; i < 4; ++i) {
                float p = Ps[sy * 4 + i][kk];
                #pragma unroll
                for (int jd = 0; jd < 8; ++jd)
                    acc[i][jd] += p * vf[jd];
            }
        }
    }

    // Epilogue: normalize and write ctx in [B,S,D] layout
    #pragma unroll
    for (int i = 0; i < 4; ++i) {
        float inv = 1.0f / lrow[i];
        int srow = qb * 64 + sy * 4 + i;
        float* outp = g_ctx + ((size_t)(b * SS + srow)) * DDIM + h * DH + sx * 8;
        float4 o0, o1;
        o0.x = acc[i][0] * inv; o0.y = acc[i][1] * inv;
        o0.z = acc[i][2] * inv; o0.w = acc[i][3] * inv;
        o1.x = acc[i][4] * inv; o1.y = acc[i][5] * inv;
        o1.z = acc[i][6] * inv; o1.w = acc[i][7] * inv;
        *(float4*)(outp + 0) = o0;
        *(float4*)(outp + 4) = o1;
    }
}

// ---------------------------------------------------------------------------
// Entry point
// Inputs: 0:q 1:k 2:v 3:mask 4:Wq 5:bq 6:Wk 7:bk 8:Wv 9:bv 10:Wo 11:bo
// ---------------------------------------------------------------------------
extern "C" void kernel_launch(void* const* d_in, const int* in_sizes, int n_in,
                              void* d_out, int out_size)
{
    const float* q  = (const float*)d_in[0];
    const float* k  = (const float*)d_in[1];
    const float* v  = (const float*)d_in[2];
    // d_in[3] = mask: causal, implemented analytically in attn_kernel
    const float* Wq = (const float*)d_in[4];
    const float* bq = (const float*)d_in[5];
    const float* Wk = (const float*)d_in[6];
    const float* bk = (const float*)d_in[7];
    const float* Wv = (const float*)d_in[8];
    const float* bv = (const float*)d_in[9];
    const float* Wo = (const float*)d_in[10];
    const float* bo = (const float*)d_in[11];
    float* out = (float*)d_out;

    float *Qh, *Kh, *Vh, *ctx;
    cudaGetSymbolAddress((void**)&Qh,  g_Qh);
    cudaGetSymbolAddress((void**)&Kh,  g_Kh);
    cudaGetSymbolAddress((void**)&Vh,  g_Vh);
    cudaGetSymbolAddress((void**)&ctx, g_ctx);

    dim3 gGrid(DDIM / 128, MM / 128);   // (8, 32)
    dim3 gBlk(256);

    gemm_bias_kernel<<<gGrid, gBlk>>>(q, Wq, bq, Qh, 1);
    gemm_bias_kernel<<<gGrid, gBlk>>>(k, Wk, bk, Kh, 1);
    gemm_bias_kernel<<<gGrid, gBlk>>>(v, Wv, bv, Vh, 1);

    attn_kernel<<<dim3(SS / 64, HH, BB), 128>>>();

    gemm_bias_kernel<<<gGrid, gBlk>>>(ctx, Wo, bo, out, 0);
}